// round 3
// baseline (speedup 1.0000x reference)
#include <cuda_runtime.h>

// Problem constants (fixed by the dataset)
#define NN      160000
#define HH      64
#define EE      3200000
#define NGENES  5000

// -------- scratch (static device globals; no runtime allocation) --------
__device__ int   g_flag;             // OR of odd 32-bit words (0 -> int64 data)
__device__ int   g_cnt[NN];          // in-degree counts
__device__ int   g_cur[NN];          // fill cursors
__device__ int   g_off[NN + 1];      // CSR offsets (by destination)
__device__ int   g_srcl[EE];         // CSR: source node per incoming edge
__device__ float g_coef[EE];         // CSR: dinv[s] * dinv[d]
__device__ float g_dinv[NN];         // (1+indeg)^-1/2
__device__ float g_invdeg[NN];       // (1+indeg)^-1
__device__ float g_hA[NN * HH];      // hW buffer (conv1 input)
__device__ float g_hB[NN * HH];      // hW buffer (conv2 input)

// ---------------------------------------------------------------------
__global__ void k_zero(int n) {
    int i = blockIdx.x * blockDim.x + threadIdx.x;
    if (i < n) { g_cnt[i] = 0; g_cur[i] = 0; }
    if (i == 0) g_flag = 0;
}

// Detect edge-index dtype: scan the first 2E int32 words; if the data is
// really int64 every odd word is a (zero) high word.  Safe for both dtypes.
__global__ void k_detect(const int* __restrict__ ei32, int E) {
    int t = blockIdx.x * blockDim.x + threadIdx.x;
    int acc = 0;
    for (long long i = 2LL * t + 1; i < 2LL * E; i += 2LL * gridDim.x * blockDim.x)
        acc |= ei32[i];
    // warp-reduce before the atomic
    #pragma unroll
    for (int o = 16; o; o >>= 1) acc |= __shfl_xor_sync(0xffffffffu, acc, o);
    if ((threadIdx.x & 31) == 0 && acc) atomicOr(&g_flag, acc);
}

__device__ __forceinline__ int ld_src(const int* __restrict__ ei32, int E, int e, bool is64) {
    int v = is64 ? ei32[2 * e] : ei32[e];
    return min(max(v, 0), NN - 1);
}
__device__ __forceinline__ int ld_dst(const int* __restrict__ ei32, int E, int e, bool is64) {
    int v = is64 ? ei32[2 * (E + e)] : ei32[E + e];
    return min(max(v, 0), NN - 1);
}

// degree accumulation over edge destinations
__global__ void k_deg(const int* __restrict__ ei32, int E) {
    int e = blockIdx.x * blockDim.x + threadIdx.x;
    bool is64 = (g_flag == 0);
    if (e < E) {
        int d = ld_dst(ei32, E, e, is64);
        atomicAdd(&g_cnt[d], 1);
    }
}

__global__ void k_dinv(int n) {
    int i = blockIdx.x * blockDim.x + threadIdx.x;
    if (i < n) {
        float d = 1.0f + (float)g_cnt[i];
        g_dinv[i]   = rsqrtf(d);
        g_invdeg[i] = 1.0f / d;
    }
}

// single-block exclusive scan over g_cnt -> g_off  (1024 threads)
__global__ void k_scan() {
    __shared__ int ssum[1024];
    const int T = 1024;
    const int per = (NN + T - 1) / T;      // 157
    int tid = threadIdx.x;
    int a = tid * per;
    int b = a + per; if (b > NN) b = NN;

    int s = 0;
    for (int i = a; i < b; i++) s += g_cnt[i];
    ssum[tid] = s;
    __syncthreads();

    for (int o = 1; o < T; o <<= 1) {
        int v = (tid >= o) ? ssum[tid - o] : 0;
        __syncthreads();
        ssum[tid] += v;
        __syncthreads();
    }

    int run = (tid == 0) ? 0 : ssum[tid - 1];
    for (int i = a; i < b; i++) { g_off[i] = run; run += g_cnt[i]; }
    if (tid == T - 1) g_off[NN] = run;
}

// CSR fill: bucket edges by destination; precompute the GCN coefficient
__global__ void k_fill(const int* __restrict__ ei32, int E) {
    int e = blockIdx.x * blockDim.x + threadIdx.x;
    bool is64 = (g_flag == 0);
    if (e < E) {
        int s = ld_src(ei32, E, e, is64);
        int d = ld_dst(ei32, E, e, is64);
        int pos = g_off[d] + atomicAdd(&g_cur[d], 1);
        g_srcl[pos] = s;
        g_coef[pos] = g_dinv[s] * g_dinv[d];
    }
}

// ---------------------------------------------------------------------
// node features (pert/basal linears, embedding renorm, emb_trans,
// pert_base_trans) fused with hW1 = h0 @ Wc1.  64 threads/node, 4 nodes/block.
__global__ void k_node(const float* __restrict__ x,
                       const float* __restrict__ Wp, const float* __restrict__ bp,
                       const float* __restrict__ Wg, const float* __restrict__ bg,
                       const float* __restrict__ Emb,
                       const float* __restrict__ Wet, const float* __restrict__ bet,
                       const float* __restrict__ Wpb, const float* __restrict__ bpb,
                       const float* __restrict__ Wc1,
                       int n) {
    __shared__ float sh_in[4][128];
    __shared__ float sh_aux[4][64];
    __shared__ float sh_red[4][2];

    const int g = threadIdx.y;
    const int j = threadIdx.x;               // 0..63
    const int i = blockIdx.x * 4 + g;        // n divisible by 4 -> uniform

    const float basal = x[2 * i];
    const float pert  = x[2 * i + 1];

    float be = fmaf(basal, Wg[j], bg[j]);
    float pe = fmaf(pert,  Wp[j], bp[j]);

    const int gid = i % NGENES;
    float e = Emb[gid * 64 + j];

    // max_norm=1 renorm over the 64-thread group
    float ss = e * e;
    #pragma unroll
    for (int o = 16; o; o >>= 1) ss += __shfl_xor_sync(0xffffffffu, ss, o);
    if ((j & 31) == 0) sh_red[g][j >> 5] = ss;
    __syncthreads();
    float nrm = sqrtf(sh_red[g][0] + sh_red[g][1]);
    float scale = fminf(1.0f, 1.0f / fmaxf(nrm, 1e-12f));
    e *= scale;

    sh_in[g][j]      = be;
    sh_in[g][64 + j] = e;
    sh_aux[g][j]     = pe;
    __syncthreads();

    // emb_trans: t = [base_emb, e] @ Wet + bet
    float t = bet[j];
    #pragma unroll 16
    for (int k = 0; k < 128; k++) t = fmaf(sh_in[g][k], __ldg(&Wet[k * 64 + j]), t);
    __syncthreads();
    sh_in[g][j]      = t;
    sh_in[g][64 + j] = sh_aux[g][j];
    __syncthreads();

    // pert_base_trans: h = [t, pert_emb] @ Wpb + bpb
    float h = bpb[j];
    #pragma unroll 16
    for (int k = 0; k < 128; k++) h = fmaf(sh_in[g][k], __ldg(&Wpb[k * 64 + j]), h);
    __syncthreads();
    sh_in[g][j] = h;
    __syncthreads();

    // hW1 = h @ Wc1 (bias folded into finalize)
    float w = 0.0f;
    #pragma unroll 16
    for (int k = 0; k < 64; k++) w = fmaf(sh_in[g][k], __ldg(&Wc1[k * 64 + j]), w);
    g_hA[(long long)i * 64 + j] = w;
}

// ---------------------------------------------------------------------
// conv1: gather over CSR + self loop + bias + relu, fused with h1 @ Wc2
__global__ void k_conv1(const float* __restrict__ bc1,
                        const float* __restrict__ Wc2,
                        int n) {
    __shared__ float sh[4][64];
    const int g = threadIdx.y;
    const int j = threadIdx.x;
    const int i = blockIdx.x * 4 + g;

    const int o0 = g_off[i];
    const int o1 = g_off[i + 1];

    float acc = 0.0f;
    int k = o0;
    for (; k + 3 < o1; k += 4) {
        int   s0 = g_srcl[k],     s1 = g_srcl[k + 1];
        int   s2 = g_srcl[k + 2], s3 = g_srcl[k + 3];
        float c0 = g_coef[k],     c1 = g_coef[k + 1];
        float c2 = g_coef[k + 2], c3 = g_coef[k + 3];
        float v0 = g_hA[(long long)s0 * 64 + j];
        float v1 = g_hA[(long long)s1 * 64 + j];
        float v2 = g_hA[(long long)s2 * 64 + j];
        float v3 = g_hA[(long long)s3 * 64 + j];
        acc = fmaf(c0, v0, acc);
        acc = fmaf(c1, v1, acc);
        acc = fmaf(c2, v2, acc);
        acc = fmaf(c3, v3, acc);
    }
    for (; k < o1; k++)
        acc = fmaf(g_coef[k], g_hA[(long long)g_srcl[k] * 64 + j], acc);

    long long o = (long long)i * 64 + j;
    float h = acc + g_hA[o] * g_invdeg[i] + bc1[j];
    h = fmaxf(h, 0.0f);
    sh[g][j] = h;
    __syncthreads();

    float w = 0.0f;
    #pragma unroll 16
    for (int kk = 0; kk < 64; kk++) w = fmaf(sh[g][kk], __ldg(&Wc2[kk * 64 + j]), w);
    g_hB[o] = w;
}

// ---------------------------------------------------------------------
// conv2 (no relu) gather, fused with recovery MLP (64->128->64->1) + residual
__global__ void k_conv2(const float* __restrict__ x,
                        const float* __restrict__ bc2,
                        const float* __restrict__ Wr1, const float* __restrict__ br1,
                        const float* __restrict__ Wr2, const float* __restrict__ br2,
                        const float* __restrict__ Wr3, const float* __restrict__ br3,
                        float* __restrict__ out, int n) {
    __shared__ float sh_h[4][64];
    __shared__ float sh_r[4][128];
    __shared__ float sh_red[4][2];

    const int g = threadIdx.y;
    const int j = threadIdx.x;
    const int i = blockIdx.x * 4 + g;

    const int o0 = g_off[i];
    const int o1 = g_off[i + 1];

    float acc = 0.0f;
    int k = o0;
    for (; k + 3 < o1; k += 4) {
        int   s0 = g_srcl[k],     s1 = g_srcl[k + 1];
        int   s2 = g_srcl[k + 2], s3 = g_srcl[k + 3];
        float c0 = g_coef[k],     c1 = g_coef[k + 1];
        float c2 = g_coef[k + 2], c3 = g_coef[k + 3];
        float v0 = g_hB[(long long)s0 * 64 + j];
        float v1 = g_hB[(long long)s1 * 64 + j];
        float v2 = g_hB[(long long)s2 * 64 + j];
        float v3 = g_hB[(long long)s3 * 64 + j];
        acc = fmaf(c0, v0, acc);
        acc = fmaf(c1, v1, acc);
        acc = fmaf(c2, v2, acc);
        acc = fmaf(c3, v3, acc);
    }
    for (; k < o1; k++)
        acc = fmaf(g_coef[k], g_hB[(long long)g_srcl[k] * 64 + j], acc);

    long long o = (long long)i * 64 + j;
    float h = acc + g_hB[o] * g_invdeg[i] + bc2[j];
    sh_h[g][j] = h;
    __syncthreads();

    // r1 = relu(h @ Wr1 + br1)   (thread j produces outputs j and j+64)
    float a = br1[j], b = br1[64 + j];
    #pragma unroll 16
    for (int kk = 0; kk < 64; kk++) {
        float hv = sh_h[g][kk];
        a = fmaf(hv, __ldg(&Wr1[kk * 128 + j]),      a);
        b = fmaf(hv, __ldg(&Wr1[kk * 128 + 64 + j]), b);
    }
    sh_r[g][j]      = fmaxf(a, 0.0f);
    sh_r[g][64 + j] = fmaxf(b, 0.0f);
    __syncthreads();

    // r2 = relu(r1 @ Wr2 + br2)
    float r2 = br2[j];
    #pragma unroll 16
    for (int kk = 0; kk < 128; kk++) r2 = fmaf(sh_r[g][kk], __ldg(&Wr2[kk * 64 + j]), r2);
    r2 = fmaxf(r2, 0.0f);

    // out = r2 @ Wr3 + br3 + basal
    float part = r2 * __ldg(&Wr3[j]);
    #pragma unroll
    for (int off = 16; off; off >>= 1) part += __shfl_xor_sync(0xffffffffu, part, off);
    if ((j & 31) == 0) sh_red[g][j >> 5] = part;
    __syncthreads();
    if (j == 0) out[i] = sh_red[g][0] + sh_red[g][1] + br3[0] + x[2 * i];
}

// ---------------------------------------------------------------------
extern "C" void kernel_launch(void* const* d_in, const int* in_sizes, int n_in,
                              void* d_out, int out_size) {
    const float* x    = (const float*)d_in[0];
    const int*   ei32 = (const int*)d_in[1];      // dtype detected on device
    const float* Wp  = (const float*)d_in[2];
    const float* bp  = (const float*)d_in[3];
    const float* Wg  = (const float*)d_in[4];
    const float* bg  = (const float*)d_in[5];
    const float* Emb = (const float*)d_in[6];
    const float* Wet = (const float*)d_in[7];
    const float* bet = (const float*)d_in[8];
    const float* Wpb = (const float*)d_in[9];
    const float* bpb = (const float*)d_in[10];
    const float* Wc1 = (const float*)d_in[11];
    const float* bc1 = (const float*)d_in[12];
    const float* Wc2 = (const float*)d_in[13];
    const float* bc2 = (const float*)d_in[14];
    const float* Wr1 = (const float*)d_in[15];
    const float* br1 = (const float*)d_in[16];
    const float* Wr2 = (const float*)d_in[17];
    const float* br2 = (const float*)d_in[18];
    const float* Wr3 = (const float*)d_in[19];
    const float* br3 = (const float*)d_in[20];
    float* out = (float*)d_out;

    const int n = in_sizes[0] / 2;   // 160000
    const int E = in_sizes[1] / 2;   // 3200000

    dim3 blk(64, 4);
    const int nblocks = n / 4;       // 40000

    k_zero  <<<(n + 255) / 256, 256>>>(n);
    k_detect<<<1024, 256>>>(ei32, E);
    k_deg   <<<(E + 255) / 256, 256>>>(ei32, E);
    k_dinv  <<<(n + 255) / 256, 256>>>(n);
    k_scan  <<<1, 1024>>>();
    k_fill  <<<(E + 255) / 256, 256>>>(ei32, E);

    k_node <<<nblocks, blk>>>(x, Wp, bp, Wg, bg, Emb, Wet, bet, Wpb, bpb, Wc1, n);
    k_conv1<<<nblocks, blk>>>(bc1, Wc2, n);
    k_conv2<<<nblocks, blk>>>(x, bc2, Wr1, br1, Wr2, br2, Wr3, br3, out, n);
}

// round 4
// speedup vs baseline: 1.3699x; 1.3699x over previous
#include <cuda_runtime.h>

#define NN      160000
#define HH      64
#define EE      3200000
#define NGENES  5000
#define TILE    32          // nodes per block in dense/conv kernels

// -------- scratch (static device globals; no runtime allocation) --------
__device__ int   g_flag;             // OR of odd 32-bit words (0 -> int64 data)
__device__ int   g_cnt[NN];
__device__ int   g_cur[NN];
__device__ int   g_off[NN + 1];
__device__ int   g_srcl[EE];
__device__ float g_coef[EE];
__device__ float g_dinv[NN];
__device__ float g_invdeg[NN];
__device__ float g_hA[NN * HH];      // h0 @ Wc1
__device__ float g_hB[NN * HH];      // h1 @ Wc2

// ---------------------------------------------------------------------
__global__ void k_zero(int n) {
    int i = blockIdx.x * blockDim.x + threadIdx.x;
    if (i < n) { g_cnt[i] = 0; g_cur[i] = 0; }
    if (i == 0) g_flag = 0;
}

__global__ void k_detect(const int* __restrict__ ei32, int E) {
    int t = blockIdx.x * blockDim.x + threadIdx.x;
    int acc = 0;
    for (long long i = 2LL * t + 1; i < 2LL * E; i += 2LL * gridDim.x * blockDim.x)
        acc |= ei32[i];
    #pragma unroll
    for (int o = 16; o; o >>= 1) acc |= __shfl_xor_sync(0xffffffffu, acc, o);
    if ((threadIdx.x & 31) == 0 && acc) atomicOr(&g_flag, acc);
}

__device__ __forceinline__ int ld_src(const int* __restrict__ ei32, int E, int e, bool is64) {
    int v = is64 ? ei32[2 * e] : ei32[e];
    return min(max(v, 0), NN - 1);
}
__device__ __forceinline__ int ld_dst(const int* __restrict__ ei32, int E, int e, bool is64) {
    int v = is64 ? ei32[2 * (E + e)] : ei32[E + e];
    return min(max(v, 0), NN - 1);
}

__global__ void k_deg(const int* __restrict__ ei32, int E) {
    int e = blockIdx.x * blockDim.x + threadIdx.x;
    bool is64 = (g_flag == 0);
    if (e < E) atomicAdd(&g_cnt[ld_dst(ei32, E, e, is64)], 1);
}

__global__ void k_dinv(int n) {
    int i = blockIdx.x * blockDim.x + threadIdx.x;
    if (i < n) {
        float d = 1.0f + (float)g_cnt[i];
        g_dinv[i]   = rsqrtf(d);
        g_invdeg[i] = 1.0f / d;
    }
}

__global__ void k_scan() {
    __shared__ int ssum[1024];
    const int T = 1024;
    const int per = (NN + T - 1) / T;
    int tid = threadIdx.x;
    int a = tid * per;
    int b = a + per; if (b > NN) b = NN;
    int s = 0;
    for (int i = a; i < b; i++) s += g_cnt[i];
    ssum[tid] = s;
    __syncthreads();
    for (int o = 1; o < T; o <<= 1) {
        int v = (tid >= o) ? ssum[tid - o] : 0;
        __syncthreads();
        ssum[tid] += v;
        __syncthreads();
    }
    int run = (tid == 0) ? 0 : ssum[tid - 1];
    for (int i = a; i < b; i++) { g_off[i] = run; run += g_cnt[i]; }
    if (tid == T - 1) g_off[NN] = run;
}

__global__ void k_fill(const int* __restrict__ ei32, int E) {
    int e = blockIdx.x * blockDim.x + threadIdx.x;
    bool is64 = (g_flag == 0);
    if (e < E) {
        int s = ld_src(ei32, E, e, is64);
        int d = ld_dst(ei32, E, e, is64);
        int pos = g_off[d] + atomicAdd(&g_cur[d], 1);
        g_srcl[pos] = s;
        g_coef[pos] = g_dinv[s] * g_dinv[d];
    }
}

// ---------------------------------------------------------------------
// Register-tiled GEMM helper: out[j][n] (64 x TILE), K inner, activations
// in SMEM laid out src[k*33 + n].  256 threads: jt=t&15 -> j4, ng=t>>4 -> n2.
// Weight W row-major [K][64], read as float4 (L1-hot).
__device__ __forceinline__ void gemm64(const float* __restrict__ src,
                                       const float* __restrict__ W,
                                       int K, float c[4][2], int j4, int n2) {
    c[0][0]=c[1][0]=c[2][0]=c[3][0]=0.f;
    c[0][1]=c[1][1]=c[2][1]=c[3][1]=0.f;
    #pragma unroll 4
    for (int k = 0; k < K; k++) {
        float4 w = __ldg((const float4*)&W[k * 64 + j4]);
        float a0 = src[k * 33 + n2];
        float a1 = src[k * 33 + n2 + 1];
        c[0][0] = fmaf(w.x, a0, c[0][0]);
        c[1][0] = fmaf(w.y, a0, c[1][0]);
        c[2][0] = fmaf(w.z, a0, c[2][0]);
        c[3][0] = fmaf(w.w, a0, c[3][0]);
        c[0][1] = fmaf(w.x, a1, c[0][1]);
        c[1][1] = fmaf(w.y, a1, c[1][1]);
        c[2][1] = fmaf(w.z, a1, c[2][1]);
        c[3][1] = fmaf(w.w, a1, c[3][1]);
    }
}

// ---------------------------------------------------------------------
// node features fused with hW1 = h0 @ Wc1, 32 nodes per block, 256 threads
__global__ void __launch_bounds__(256) k_node(
        const float* __restrict__ x,
        const float* __restrict__ Wp, const float* __restrict__ bp,
        const float* __restrict__ Wg, const float* __restrict__ bg,
        const float* __restrict__ Emb,
        const float* __restrict__ Wet, const float* __restrict__ bet,
        const float* __restrict__ Wpb, const float* __restrict__ bpb,
        const float* __restrict__ Wc1) {
    __shared__ float actA[128 * 33];
    __shared__ float actB[128 * 33];
    __shared__ float sb[TILE], sp[TILE], ssc[TILE];

    const int t  = threadIdx.x;
    const int i0 = blockIdx.x * TILE;

    if (t < TILE) {
        sb[t] = x[2 * (i0 + t)];
        sp[t] = x[2 * (i0 + t) + 1];
    }

    // per-node embedding renorm scale: warp w handles nodes w*4..w*4+3
    {
        int w = t >> 5, lane = t & 31;
        for (int nn = 0; nn < 4; nn++) {
            int n = w * 4 + nn;
            int gid = (i0 + n) % NGENES;
            float e0 = Emb[gid * 64 + lane];
            float e1 = Emb[gid * 64 + 32 + lane];
            float ss = e0 * e0 + e1 * e1;
            #pragma unroll
            for (int o = 16; o; o >>= 1) ss += __shfl_xor_sync(0xffffffffu, ss, o);
            if (lane == 0) {
                float nrm = sqrtf(ss);
                ssc[n] = fminf(1.0f, 1.0f / fmaxf(nrm, 1e-12f));
            }
        }
    }
    __syncthreads();

    // fill actA = [be ; e_renorm], actB rows 64..127 = pe
    #pragma unroll
    for (int it = 0; it < 8; it++) {
        int idx = t + 256 * it;          // 0..2047
        int j = idx & 63;
        int n = idx >> 6;
        int i = i0 + n;
        actA[j * 33 + n]        = fmaf(sb[n], __ldg(&Wg[j]), __ldg(&bg[j]));
        int gid = i % NGENES;
        actA[(64 + j) * 33 + n] = __ldg(&Emb[gid * 64 + j]) * ssc[n];
        actB[(64 + j) * 33 + n] = fmaf(sp[n], __ldg(&Wp[j]), __ldg(&bp[j]));
    }
    __syncthreads();

    const int jt = t & 15, ng = t >> 4;
    const int j4 = jt * 4, n2 = ng * 2;
    float c[4][2];

    // stage 1: t = [be;e] @ Wet + bet  -> actB rows 0..63
    gemm64(actA, Wet, 128, c, j4, n2);
    __syncthreads();
    #pragma unroll
    for (int jj = 0; jj < 4; jj++) {
        float bb = __ldg(&bet[j4 + jj]);
        actB[(j4 + jj) * 33 + n2]     = c[jj][0] + bb;
        actB[(j4 + jj) * 33 + n2 + 1] = c[jj][1] + bb;
    }
    __syncthreads();

    // stage 2: h = [t;pe] @ Wpb + bpb -> actA rows 0..63
    gemm64(actB, Wpb, 128, c, j4, n2);
    __syncthreads();
    #pragma unroll
    for (int jj = 0; jj < 4; jj++) {
        float bb = __ldg(&bpb[j4 + jj]);
        actA[(j4 + jj) * 33 + n2]     = c[jj][0] + bb;
        actA[(j4 + jj) * 33 + n2 + 1] = c[jj][1] + bb;
    }
    __syncthreads();

    // stage 3: w = h @ Wc1 -> g_hA
    gemm64(actA, Wc1, 64, c, j4, n2);
    #pragma unroll
    for (int nn = 0; nn < 2; nn++) {
        float4 v = make_float4(c[0][nn], c[1][nn], c[2][nn], c[3][nn]);
        *(float4*)&g_hA[(size_t)(i0 + n2 + nn) * 64 + j4] = v;
    }
}

// ---------------------------------------------------------------------
// CSR gather into SMEM act[j*33+n] with self-loop+bias (+optional relu)
__device__ __forceinline__ void gather_tile(const float* __restrict__ hSrc,
                                            const float* __restrict__ bias,
                                            bool relu, int i0, int t,
                                            float* __restrict__ act) {
    const int g = t >> 6;     // 0..3
    const int j = t & 63;
    const float bj = __ldg(&bias[j]);
    for (int q = 0; q < 8; q++) {
        int n = g * 8 + q;
        int i = i0 + n;
        int o0 = g_off[i], o1 = g_off[i + 1];
        float acc = 0.0f;
        int k = o0;
        for (; k + 3 < o1; k += 4) {
            int   s0 = g_srcl[k],     s1 = g_srcl[k + 1];
            int   s2 = g_srcl[k + 2], s3 = g_srcl[k + 3];
            float c0 = g_coef[k],     c1 = g_coef[k + 1];
            float c2 = g_coef[k + 2], c3 = g_coef[k + 3];
            float v0 = hSrc[s0 * 64 + j];
            float v1 = hSrc[s1 * 64 + j];
            float v2 = hSrc[s2 * 64 + j];
            float v3 = hSrc[s3 * 64 + j];
            acc = fmaf(c0, v0, acc);
            acc = fmaf(c1, v1, acc);
            acc = fmaf(c2, v2, acc);
            acc = fmaf(c3, v3, acc);
        }
        for (; k < o1; k++)
            acc = fmaf(g_coef[k], hSrc[g_srcl[k] * 64 + j], acc);
        float h = acc + hSrc[(size_t)i * 64 + j] * g_invdeg[i] + bj;
        act[j * 33 + n] = relu ? fmaxf(h, 0.0f) : h;
    }
}

// conv1: gather(hA)+relu fused with @Wc2 -> g_hB
__global__ void __launch_bounds__(256) k_conv1(const float* __restrict__ bc1,
                                               const float* __restrict__ Wc2) {
    __shared__ float act[64 * 33];
    const int t  = threadIdx.x;
    const int i0 = blockIdx.x * TILE;

    gather_tile(g_hA, bc1, true, i0, t, act);
    __syncthreads();

    const int jt = t & 15, ng = t >> 4;
    const int j4 = jt * 4, n2 = ng * 2;
    float c[4][2];
    gemm64(act, Wc2, 64, c, j4, n2);
    #pragma unroll
    for (int nn = 0; nn < 2; nn++) {
        float4 v = make_float4(c[0][nn], c[1][nn], c[2][nn], c[3][nn]);
        *(float4*)&g_hB[(size_t)(i0 + n2 + nn) * 64 + j4] = v;
    }
}

// conv2: gather(hB) fused with recovery MLP (64->128->64->1) + residual
__global__ void __launch_bounds__(256) k_conv2(
        const float* __restrict__ x,
        const float* __restrict__ bc2,
        const float* __restrict__ Wr1, const float* __restrict__ br1,
        const float* __restrict__ Wr2, const float* __restrict__ br2,
        const float* __restrict__ Wr3, const float* __restrict__ br3,
        float* __restrict__ out) {
    __shared__ float hbuf[64 * 33];
    __shared__ float r1[128 * 33];
    __shared__ float red[TILE];

    const int t  = threadIdx.x;
    const int i0 = blockIdx.x * TILE;

    gather_tile(g_hB, bc2, false, i0, t, hbuf);
    __syncthreads();

    // r1 = relu(h @ Wr1 + br1): out 128 x 32, tile 4j x 4n
    {
        const int jt = t & 31, ng = t >> 5;
        const int j4 = jt * 4, n4 = ng * 4;
        float c[4][4];
        #pragma unroll
        for (int a = 0; a < 4; a++)
            #pragma unroll
            for (int b = 0; b < 4; b++) c[a][b] = 0.f;
        #pragma unroll 2
        for (int k = 0; k < 64; k++) {
            float4 w = __ldg((const float4*)&Wr1[k * 128 + j4]);
            float a0 = hbuf[k * 33 + n4];
            float a1 = hbuf[k * 33 + n4 + 1];
            float a2 = hbuf[k * 33 + n4 + 2];
            float a3 = hbuf[k * 33 + n4 + 3];
            c[0][0]=fmaf(w.x,a0,c[0][0]); c[1][0]=fmaf(w.y,a0,c[1][0]);
            c[2][0]=fmaf(w.z,a0,c[2][0]); c[3][0]=fmaf(w.w,a0,c[3][0]);
            c[0][1]=fmaf(w.x,a1,c[0][1]); c[1][1]=fmaf(w.y,a1,c[1][1]);
            c[2][1]=fmaf(w.z,a1,c[2][1]); c[3][1]=fmaf(w.w,a1,c[3][1]);
            c[0][2]=fmaf(w.x,a2,c[0][2]); c[1][2]=fmaf(w.y,a2,c[1][2]);
            c[2][2]=fmaf(w.z,a2,c[2][2]); c[3][2]=fmaf(w.w,a2,c[3][2]);
            c[0][3]=fmaf(w.x,a3,c[0][3]); c[1][3]=fmaf(w.y,a3,c[1][3]);
            c[2][3]=fmaf(w.z,a3,c[2][3]); c[3][3]=fmaf(w.w,a3,c[3][3]);
        }
        __syncthreads();
        #pragma unroll
        for (int jj = 0; jj < 4; jj++) {
            float bb = __ldg(&br1[j4 + jj]);
            #pragma unroll
            for (int nn = 0; nn < 4; nn++)
                r1[(j4 + jj) * 33 + n4 + nn] = fmaxf(c[jj][nn] + bb, 0.0f);
        }
    }
    __syncthreads();

    // r2 = relu(r1 @ Wr2 + br2) then dot with Wr3
    {
        const int jt = t & 15, ng = t >> 4;
        const int j4 = jt * 4, n2 = ng * 2;
        float c[4][2];
        gemm64(r1, Wr2, 128, c, j4, n2);

        float p0 = 0.f, p1 = 0.f;
        #pragma unroll
        for (int jj = 0; jj < 4; jj++) {
            float bb = __ldg(&br2[j4 + jj]);
            float w3 = __ldg(&Wr3[j4 + jj]);
            p0 = fmaf(fmaxf(c[jj][0] + bb, 0.f), w3, p0);
            p1 = fmaf(fmaxf(c[jj][1] + bb, 0.f), w3, p1);
        }
        // reduce over jt (lane bits 0..3)
        #pragma unroll
        for (int o = 1; o <= 8; o <<= 1) {
            p0 += __shfl_xor_sync(0xffffffffu, p0, o);
            p1 += __shfl_xor_sync(0xffffffffu, p1, o);
        }
        if (jt == 0) { red[n2] = p0; red[n2 + 1] = p1; }
    }
    __syncthreads();

    if (t < TILE)
        out[i0 + t] = red[t] + __ldg(&br3[0]) + x[2 * (i0 + t)];
}

// ---------------------------------------------------------------------
extern "C" void kernel_launch(void* const* d_in, const int* in_sizes, int n_in,
                              void* d_out, int out_size) {
    const float* x    = (const float*)d_in[0];
    const int*   ei32 = (const int*)d_in[1];
    const float* Wp  = (const float*)d_in[2];
    const float* bp  = (const float*)d_in[3];
    const float* Wg  = (const float*)d_in[4];
    const float* bg  = (const float*)d_in[5];
    const float* Emb = (const float*)d_in[6];
    const float* Wet = (const float*)d_in[7];
    const float* bet = (const float*)d_in[8];
    const float* Wpb = (const float*)d_in[9];
    const float* bpb = (const float*)d_in[10];
    const float* Wc1 = (const float*)d_in[11];
    const float* bc1 = (const float*)d_in[12];
    const float* Wc2 = (const float*)d_in[13];
    const float* bc2 = (const float*)d_in[14];
    const float* Wr1 = (const float*)d_in[15];
    const float* br1 = (const float*)d_in[16];
    const float* Wr2 = (const float*)d_in[17];
    const float* br2 = (const float*)d_in[18];
    const float* Wr3 = (const float*)d_in[19];
    const float* br3 = (const float*)d_in[20];
    float* out = (float*)d_out;

    const int n = in_sizes[0] / 2;   // 160000
    const int E = in_sizes[1] / 2;   // 3200000
    const int nblocks = n / TILE;    // 5000

    k_zero  <<<(n + 255) / 256, 256>>>(n);
    k_detect<<<1024, 256>>>(ei32, E);
    k_deg   <<<(E + 255) / 256, 256>>>(ei32, E);
    k_dinv  <<<(n + 255) / 256, 256>>>(n);
    k_scan  <<<1, 1024>>>();
    k_fill  <<<(E + 255) / 256, 256>>>(ei32, E);

    k_node <<<nblocks, 256>>>(x, Wp, bp, Wg, bg, Emb, Wet, bet, Wpb, bpb, Wc1);
    k_conv1<<<nblocks, 256>>>(bc1, Wc2);
    k_conv2<<<nblocks, 256>>>(x, bc2, Wr1, br1, Wr2, br2, Wr3, br3, out);
}

// round 5
// speedup vs baseline: 1.8546x; 1.3538x over previous
#include <cuda_runtime.h>

#define NN      160000
#define HH      64
#define EE      3200000
#define NGENES  5000
#define TILE    32

// -------- scratch (static device globals; no runtime allocation) --------
__device__ int   g_flag;
__device__ int   g_cnt[NN];
__device__ int   g_cur[NN];
__device__ int   g_off[NN + 1];
__device__ int   g_srcl[EE];
__device__ float g_dinv[NN];
__device__ float g_hA[NN * HH];      // scaled h0@Wc1
__device__ float g_hB[NN * HH];      // scaled h1@Wc2
// precompute scratch
__device__ float g_Wtc[64 * 64];     // WpbT @ Wc1
__device__ float g_Wtot[64 * 64];    // WetB @ Wtc
__device__ float g_E3[NGENES * 64];  // renorm(Emb) @ Wtot
__device__ float g_P[64], g_Q[64], g_R[64];

// ---------------- f32x2 packed-FMA helpers ----------------
#define FFMA2(c, a, b) asm("fma.rn.f32x2 %0, %1, %2, %0;" : "+l"(c) : "l"(a), "l"(b))
#define DUP2(d, s) asm("mov.b64 %0, {%1, %2};" : "=l"(d) \
                       : "r"(__float_as_uint(s)), "r"(__float_as_uint(s)))
__device__ __forceinline__ void unpack2(float& lo, float& hi, unsigned long long s) {
    unsigned int ulo, uhi;
    asm("mov.b64 {%0, %1}, %2;" : "=r"(ulo), "=r"(uhi) : "l"(s));
    lo = __uint_as_float(ulo); hi = __uint_as_float(uhi);
}

// ---------------------------------------------------------------------
__global__ void k_zero(int n) {
    int i = blockIdx.x * blockDim.x + threadIdx.x;
    if (i < n) { g_cnt[i] = 0; g_cur[i] = 0; }
    if (i == 0) g_flag = 0;
}

__global__ void k_detect(const int* __restrict__ ei32, int E) {
    int t = blockIdx.x * blockDim.x + threadIdx.x;
    int acc = 0;
    for (long long i = 2LL * t + 1; i < 2LL * E; i += 2LL * gridDim.x * blockDim.x)
        acc |= ei32[i];
    #pragma unroll
    for (int o = 16; o; o >>= 1) acc |= __shfl_xor_sync(0xffffffffu, acc, o);
    if ((threadIdx.x & 31) == 0 && acc) atomicOr(&g_flag, acc);
}

__device__ __forceinline__ int ld_src(const int* __restrict__ ei32, int E, int e, bool is64) {
    int v = is64 ? ei32[2 * e] : ei32[e];
    return min(max(v, 0), NN - 1);
}
__device__ __forceinline__ int ld_dst(const int* __restrict__ ei32, int E, int e, bool is64) {
    int v = is64 ? ei32[2 * (E + e)] : ei32[E + e];
    return min(max(v, 0), NN - 1);
}

__global__ void k_deg(const int* __restrict__ ei32, int E) {
    int e = blockIdx.x * blockDim.x + threadIdx.x;
    bool is64 = (g_flag == 0);
    if (e < E) atomicAdd(&g_cnt[ld_dst(ei32, E, e, is64)], 1);
}

__global__ void k_dinv(int n) {
    int i = blockIdx.x * blockDim.x + threadIdx.x;
    if (i < n) g_dinv[i] = rsqrtf(1.0f + (float)g_cnt[i]);
}

__global__ void k_scan() {
    __shared__ int ssum[1024];
    const int T = 1024;
    const int per = (NN + T - 1) / T;
    int tid = threadIdx.x;
    int a = tid * per;
    int b = a + per; if (b > NN) b = NN;
    int s = 0;
    for (int i = a; i < b; i++) s += g_cnt[i];
    ssum[tid] = s;
    __syncthreads();
    for (int o = 1; o < T; o <<= 1) {
        int v = (tid >= o) ? ssum[tid - o] : 0;
        __syncthreads();
        ssum[tid] += v;
        __syncthreads();
    }
    int run = (tid == 0) ? 0 : ssum[tid - 1];
    for (int i = a; i < b; i++) { g_off[i] = run; run += g_cnt[i]; }
    if (tid == T - 1) g_off[NN] = run;
}

__global__ void k_fill(const int* __restrict__ ei32, int E) {
    int e = blockIdx.x * blockDim.x + threadIdx.x;
    bool is64 = (g_flag == 0);
    if (e < E) {
        int s = ld_src(ei32, E, e, is64);
        int d = ld_dst(ei32, E, e, is64);
        g_srcl[g_off[d] + atomicAdd(&g_cur[d], 1)] = s;
    }
}

// ---------------------------------------------------------------------
// p1: fold all affine pre-GCN transforms.  Single block, 256 threads.
//   Wtc  = Wpb[0:64]  @ Wc1
//   Wtot = Wet[64:128] @ Wtc
//   P = (Wg @ Wet[0:64]) @ Wtc          (basal direction)
//   Q = (Wp @ Wpb[64:128]) @ Wc1        (pert direction)
//   R = ((bg@Wet[0:64]+bet)@Wpb[0:64] + bp@Wpb[64:128] + bpb) @ Wc1
__global__ void __launch_bounds__(256) k_pre1(
        const float* __restrict__ Wp, const float* __restrict__ bp,
        const float* __restrict__ Wg, const float* __restrict__ bg,
        const float* __restrict__ Wet, const float* __restrict__ bet,
        const float* __restrict__ Wpb, const float* __restrict__ bpb,
        const float* __restrict__ Wc1) {
    __shared__ float sv[64];
    const int t = threadIdx.x;
    const int j = t & 63, q = t >> 6;      // q = 0..3

    // Wtc rows q*16 .. q*16+15, column j
    for (int r = q * 16; r < q * 16 + 16; r++) {
        float s = 0.f;
        #pragma unroll 4
        for (int k = 0; k < 64; k++) s = fmaf(Wpb[r * 64 + k], Wc1[k * 64 + j], s);
        g_Wtc[r * 64 + j] = s;
    }
    __syncthreads();
    for (int r = q * 16; r < q * 16 + 16; r++) {
        float s = 0.f;
        #pragma unroll 4
        for (int k = 0; k < 64; k++) s = fmaf(Wet[(64 + r) * 64 + k], g_Wtc[k * 64 + j], s);
        g_Wtot[r * 64 + j] = s;
    }
    // P
    if (q == 0) {
        float u = 0.f;
        for (int k = 0; k < 64; k++) u = fmaf(Wg[k], Wet[k * 64 + j], u);
        sv[j] = u;
    }
    __syncthreads();
    if (q == 0) {
        float p = 0.f;
        for (int k = 0; k < 64; k++) p = fmaf(sv[k], g_Wtc[k * 64 + j], p);
        g_P[j] = p;
    }
    __syncthreads();
    // Q
    if (q == 1) {
        float v = 0.f;
        for (int k = 0; k < 64; k++) v = fmaf(Wp[k], Wpb[(64 + k) * 64 + j], v);
        sv[j] = v;
    }
    __syncthreads();
    if (q == 1) {
        float qq = 0.f;
        for (int k = 0; k < 64; k++) qq = fmaf(sv[k], Wc1[k * 64 + j], qq);
        g_Q[j] = qq;
    }
    __syncthreads();
    // R
    if (q == 2) {
        float r1 = bet[j];
        for (int k = 0; k < 64; k++) r1 = fmaf(bg[k], Wet[k * 64 + j], r1);
        sv[j] = r1;
    }
    __syncthreads();
    if (q == 2) {
        float r2 = bpb[j];
        for (int k = 0; k < 64; k++) r2 = fmaf(sv[k], Wpb[k * 64 + j], r2);
        for (int k = 0; k < 64; k++) r2 = fmaf(bp[k], Wpb[(64 + k) * 64 + j], r2);
        sv[j] = r2;
    }
    __syncthreads();
    if (q == 2) {
        float rr = 0.f;
        for (int k = 0; k < 64; k++) rr = fmaf(sv[k], Wc1[k * 64 + j], rr);
        g_R[j] = rr;
    }
}

// p2: E3[g] = renorm(Emb[g]) @ Wtot   (4 genes per block)
__global__ void __launch_bounds__(256) k_pre2(const float* __restrict__ Emb) {
    __shared__ float se[4][64];
    __shared__ float ssc[4];
    const int t = threadIdx.x;
    const int gl = t >> 6, j = t & 63;
    const int g = blockIdx.x * 4 + gl;
    if (g >= NGENES) return;

    float e = Emb[g * 64 + j];
    se[gl][j] = e;
    float ss = e * e;
    #pragma unroll
    for (int o = 16; o; o >>= 1) ss += __shfl_xor_sync(0xffffffffu, ss, o);
    __shared__ float sp[4][2];
    if ((j & 31) == 0) sp[gl][j >> 5] = ss;
    __syncthreads();
    if (j == 0) {
        float nrm = sqrtf(sp[gl][0] + sp[gl][1]);
        ssc[gl] = fminf(1.0f, 1.0f / fmaxf(nrm, 1e-12f));
    }
    __syncthreads();

    float acc = 0.f;
    #pragma unroll 4
    for (int k = 0; k < 64; k++) acc = fmaf(se[gl][k], g_Wtot[k * 64 + j], acc);
    g_E3[g * 64 + j] = acc * ssc[gl];
}

// node kernel: hA[i] = (E3[gid] + basal*P + pert*Q + R) * dinv[i]
__global__ void __launch_bounds__(256) k_node(const float* __restrict__ x) {
    const int t = threadIdx.x;
    const int i = blockIdx.x * 4 + (t >> 6);
    const int j = t & 63;
    const float basal = __ldg(&x[2 * i]);
    const float pert  = __ldg(&x[2 * i + 1]);
    const int gid = i % NGENES;
    float w = g_E3[gid * 64 + j] + basal * g_P[j] + pert * g_Q[j] + g_R[j];
    g_hA[i * 64 + j] = w * g_dinv[i];
}

// ---------------------------------------------------------------------
// gather: warp-per-node, float2 lanes.  Sums scaled rows (incl. own row),
// multiplies by dinv[d], adds bias, optional relu, writes act[j*33+n].
__device__ __forceinline__ void gather_tile(const float* __restrict__ hSrc,
                                            const float* __restrict__ bias,
                                            bool relu, int i0,
                                            float* __restrict__ act) {
    const int lane = threadIdx.x & 31;
    const int w    = threadIdx.x >> 5;       // 0..7
    const float2 bj = *(const float2*)&bias[2 * lane];
    for (int r = 0; r < 4; r++) {
        const int n = w * 4 + r;
        const int i = i0 + n;
        const int o0 = g_off[i];
        const int D  = g_off[i + 1] - o0;

        float2 a0 = *(const float2*)&hSrc[i * 64 + 2 * lane];  // own row
        float2 a1 = make_float2(0.f, 0.f);
        float2 a2 = make_float2(0.f, 0.f);
        float2 a3 = make_float2(0.f, 0.f);

        int base = o0;
        const int nfull = D >> 5;
        for (int c = 0; c < nfull; c++) {
            int idx = g_srcl[base + lane];
            base += 32;
            #pragma unroll 8
            for (int e = 0; e < 32; e++) {
                int s = __shfl_sync(0xffffffffu, idx, e);
                float2 v = *(const float2*)&hSrc[s * 64 + 2 * lane];
                if ((e & 3) == 0)      { a0.x += v.x; a0.y += v.y; }
                else if ((e & 3) == 1) { a1.x += v.x; a1.y += v.y; }
                else if ((e & 3) == 2) { a2.x += v.x; a2.y += v.y; }
                else                   { a3.x += v.x; a3.y += v.y; }
            }
        }
        const int rem = D & 31;
        if (rem) {
            int idx = (lane < rem) ? g_srcl[base + lane] : 0;
            for (int e = 0; e < rem; e++) {
                int s = __shfl_sync(0xffffffffu, idx, e);
                float2 v = *(const float2*)&hSrc[s * 64 + 2 * lane];
                if ((e & 1) == 0) { a0.x += v.x; a0.y += v.y; }
                else              { a1.x += v.x; a1.y += v.y; }
            }
        }
        float di = g_dinv[i];
        float h0 = (a0.x + a1.x + a2.x + a3.x) * di + bj.x;
        float h1 = (a0.y + a1.y + a2.y + a3.y) * di + bj.y;
        if (relu) { h0 = fmaxf(h0, 0.f); h1 = fmaxf(h1, 0.f); }
        act[(2 * lane) * 33 + n]     = h0;
        act[(2 * lane + 1) * 33 + n] = h1;
    }
}

// f32x2 GEMM tile: 4j x 2n per thread; W row-major [K][64]
__device__ __forceinline__ void gemm2_64(const float* __restrict__ src,
                                         const float* __restrict__ W, int K,
                                         unsigned long long c[4], int j4, int n2) {
    c[0] = c[1] = c[2] = c[3] = 0ULL;
    #pragma unroll 4
    for (int k = 0; k < K; k++) {
        ulonglong2 w = __ldg((const ulonglong2*)&W[k * 64 + j4]);
        float av0 = src[k * 33 + n2];
        float av1 = src[k * 33 + n2 + 1];
        unsigned long long a00, a11;
        DUP2(a00, av0); DUP2(a11, av1);
        FFMA2(c[0], w.x, a00);
        FFMA2(c[1], w.y, a00);
        FFMA2(c[2], w.x, a11);
        FFMA2(c[3], w.y, a11);
    }
}

// conv1: gather(hA)+relu -> @Wc2 (f32x2) -> scale by dinv -> hB
__global__ void __launch_bounds__(256) k_conv1(const float* __restrict__ bc1,
                                               const float* __restrict__ Wc2) {
    __shared__ float act[64 * 33];
    const int t  = threadIdx.x;
    const int i0 = blockIdx.x * TILE;

    gather_tile(g_hA, bc1, true, i0, act);
    __syncthreads();

    const int jt = t & 15, ng = t >> 4;
    const int j4 = jt * 4, n2 = ng * 2;
    unsigned long long c[4];
    gemm2_64(act, Wc2, 64, c, j4, n2);

    float v0, v1, v2, v3;
    float d0 = g_dinv[i0 + n2], d1 = g_dinv[i0 + n2 + 1];
    unpack2(v0, v1, c[0]); unpack2(v2, v3, c[1]);
    *(float4*)&g_hB[(i0 + n2) * 64 + j4] = make_float4(v0 * d0, v1 * d0, v2 * d0, v3 * d0);
    unpack2(v0, v1, c[2]); unpack2(v2, v3, c[3]);
    *(float4*)&g_hB[(i0 + n2 + 1) * 64 + j4] = make_float4(v0 * d1, v1 * d1, v2 * d1, v3 * d1);
}

// conv2: gather(hB) -> recovery MLP (64->128->64->1) + residual
__global__ void __launch_bounds__(256) k_conv2(
        const float* __restrict__ x,
        const float* __restrict__ bc2,
        const float* __restrict__ Wr1, const float* __restrict__ br1,
        const float* __restrict__ Wr2, const float* __restrict__ br2,
        const float* __restrict__ Wr3, const float* __restrict__ br3,
        float* __restrict__ out) {
    __shared__ float hbuf[64 * 33];
    __shared__ float r1[128 * 33];
    __shared__ float red[TILE];

    const int t  = threadIdx.x;
    const int i0 = blockIdx.x * TILE;

    gather_tile(g_hB, bc2, false, i0, hbuf);
    __syncthreads();

    // r1 = relu(h @ Wr1 + br1): 8j x 2n tiles (Wr1 stride 128)
    {
        const int jt = t & 15, ng = t >> 4;
        const int j8 = jt * 8, n2 = ng * 2;
        unsigned long long c[8];
        #pragma unroll
        for (int a = 0; a < 8; a++) c[a] = 0ULL;
        #pragma unroll 2
        for (int k = 0; k < 64; k++) {
            ulonglong2 wa = __ldg((const ulonglong2*)&Wr1[k * 128 + j8]);
            ulonglong2 wb = __ldg((const ulonglong2*)&Wr1[k * 128 + j8 + 4]);
            float av0 = hbuf[k * 33 + n2];
            float av1 = hbuf[k * 33 + n2 + 1];
            unsigned long long a00, a11;
            DUP2(a00, av0); DUP2(a11, av1);
            FFMA2(c[0], wa.x, a00); FFMA2(c[1], wa.y, a00);
            FFMA2(c[2], wb.x, a00); FFMA2(c[3], wb.y, a00);
            FFMA2(c[4], wa.x, a11); FFMA2(c[5], wa.y, a11);
            FFMA2(c[6], wb.x, a11); FFMA2(c[7], wb.y, a11);
        }
        __syncthreads();
        #pragma unroll
        for (int p = 0; p < 4; p++) {
            float v0, v1;
            float b0 = __ldg(&br1[j8 + 2 * p]);
            float b1 = __ldg(&br1[j8 + 2 * p + 1]);
            unpack2(v0, v1, c[p]);
            r1[(j8 + 2 * p) * 33 + n2]     = fmaxf(v0 + b0, 0.f);
            r1[(j8 + 2 * p + 1) * 33 + n2] = fmaxf(v1 + b1, 0.f);
            unpack2(v0, v1, c[4 + p]);
            r1[(j8 + 2 * p) * 33 + n2 + 1]     = fmaxf(v0 + b0, 0.f);
            r1[(j8 + 2 * p + 1) * 33 + n2 + 1] = fmaxf(v1 + b1, 0.f);
        }
    }
    __syncthreads();

    // r2 = relu(r1 @ Wr2 + br2), then dot Wr3 and reduce
    {
        const int jt = t & 15, ng = t >> 4;
        const int j4 = jt * 4, n2 = ng * 2;
        unsigned long long c[4];
        gemm2_64(r1, Wr2, 128, c, j4, n2);

        float v[4][2];
        unpack2(v[0][0], v[1][0], c[0]); unpack2(v[2][0], v[3][0], c[1]);
        unpack2(v[0][1], v[1][1], c[2]); unpack2(v[2][1], v[3][1], c[3]);

        float p0 = 0.f, p1 = 0.f;
        #pragma unroll
        for (int jj = 0; jj < 4; jj++) {
            float bb = __ldg(&br2[j4 + jj]);
            float w3 = __ldg(&Wr3[j4 + jj]);
            p0 = fmaf(fmaxf(v[jj][0] + bb, 0.f), w3, p0);
            p1 = fmaf(fmaxf(v[jj][1] + bb, 0.f), w3, p1);
        }
        #pragma unroll
        for (int o = 1; o <= 8; o <<= 1) {
            p0 += __shfl_xor_sync(0xffffffffu, p0, o);
            p1 += __shfl_xor_sync(0xffffffffu, p1, o);
        }
        if (jt == 0) { red[n2] = p0; red[n2 + 1] = p1; }
    }
    __syncthreads();

    if (t < TILE)
        out[i0 + t] = red[t] + __ldg(&br3[0]) + x[2 * (i0 + t)];
}

// ---------------------------------------------------------------------
extern "C" void kernel_launch(void* const* d_in, const int* in_sizes, int n_in,
                              void* d_out, int out_size) {
    const float* x    = (const float*)d_in[0];
    const int*   ei32 = (const int*)d_in[1];
    const float* Wp  = (const float*)d_in[2];
    const float* bp  = (const float*)d_in[3];
    const float* Wg  = (const float*)d_in[4];
    const float* bg  = (const float*)d_in[5];
    const float* Emb = (const float*)d_in[6];
    const float* Wet = (const float*)d_in[7];
    const float* bet = (const float*)d_in[8];
    const float* Wpb = (const float*)d_in[9];
    const float* bpb = (const float*)d_in[10];
    const float* Wc1 = (const float*)d_in[11];
    const float* bc1 = (const float*)d_in[12];
    const float* Wc2 = (const float*)d_in[13];
    const float* bc2 = (const float*)d_in[14];
    const float* Wr1 = (const float*)d_in[15];
    const float* br1 = (const float*)d_in[16];
    const float* Wr2 = (const float*)d_in[17];
    const float* br2 = (const float*)d_in[18];
    const float* Wr3 = (const float*)d_in[19];
    const float* br3 = (const float*)d_in[20];
    float* out = (float*)d_out;

    const int n = in_sizes[0] / 2;   // 160000
    const int E = in_sizes[1] / 2;   // 3200000
    const int nblocks = n / TILE;    // 5000

    k_pre1  <<<1, 256>>>(Wp, bp, Wg, bg, Wet, bet, Wpb, bpb, Wc1);
    k_zero  <<<(n + 255) / 256, 256>>>(n);
    k_detect<<<1024, 256>>>(ei32, E);
    k_deg   <<<(E + 255) / 256, 256>>>(ei32, E);
    k_dinv  <<<(n + 255) / 256, 256>>>(n);
    k_scan  <<<1, 1024>>>();
    k_fill  <<<(E + 255) / 256, 256>>>(ei32, E);
    k_pre2  <<<(NGENES + 3) / 4, 256>>>(Emb);

    k_node <<<n / 4, 256>>>(x);
    k_conv1<<<nblocks, 256>>>(bc1, Wc2);
    k_conv2<<<nblocks, 256>>>(x, bc2, Wr1, br1, Wr2, br2, Wr3, br3, out);
}